// round 14
// baseline (speedup 1.0000x reference)
#include <cuda_runtime.h>
#include <cuda_bf16.h>

#define SLEN 2048
#define NH   16
#define HD   64
#define QT   128
#define KT   32
#define NT   256
#define LOG2E 1.4426950408889634f
#define FIXM 12.0f

// smem stage layout (KT=32): K tiles 32x72 bf16, V^T tiles 64x40 bf16
#define STRK 72
#define STRV 40
#define OFF_KH 0
#define OFF_KL 4608
#define OFF_VH 9216
#define OFF_VL 14336
#define OFF_DJ 19456
#define STAGE  19584
#define SMEM_BYTES (2 * STAGE)   // 39168 -> 2 CTAs/SM easily

// Scratch (allocation-free rule) — layouts identical to R7/R12
__device__ __nv_bfloat16 g_Kh [NH * SLEN * HD];   // K rows [h][j][d], hi
__device__ __nv_bfloat16 g_Kl [NH * SLEN * HD];
__device__ __nv_bfloat16 g_VtH[NH * HD * SLEN];   // V transposed [h][d][j]
__device__ __nv_bfloat16 g_VtL[NH * HD * SLEN];
__device__ float g_posf[SLEN];
__device__ int   g_pos [SLEN];
__device__ int   g_nvalid;

// ---- helpers ----------------------------------------------------------------
__device__ __forceinline__ unsigned smem_u32(const void* p) {
    return (unsigned)__cvta_generic_to_shared(p);
}
__device__ __forceinline__ float ex2(float x) {
    float r; asm("ex2.approx.f32 %0, %1;" : "=f"(r) : "f"(x)); return r;
}
__device__ __forceinline__ void splitpack(float x0, float x1, unsigned& hp, unsigned& lp) {
    __nv_bfloat16 h0 = __float2bfloat16(x0), h1 = __float2bfloat16(x1);
    float r0 = x0 - __bfloat162float(h0), r1 = x1 - __bfloat162float(h1);
    __nv_bfloat16 l0 = __float2bfloat16(r0), l1 = __float2bfloat16(r1);
    hp = ((unsigned)__bfloat16_as_ushort(h1) << 16) | (unsigned)__bfloat16_as_ushort(h0);
    lp = ((unsigned)__bfloat16_as_ushort(l1) << 16) | (unsigned)__bfloat16_as_ushort(l0);
}
__device__ __forceinline__ void cp16(unsigned dst, const void* src) {
    asm volatile("cp.async.cg.shared.global [%0], [%1], 16;" :: "r"(dst), "l"(src));
}
__device__ __forceinline__ void cp_commit() { asm volatile("cp.async.commit_group;"); }
template<int N> __device__ __forceinline__ void cp_wait() {
    asm volatile("cp.async.wait_group %0;" :: "n"(N));
}
__device__ __forceinline__ void mma_bf16(float (&d)[4], const unsigned (&a)[4],
                                         unsigned b0, unsigned b1) {
    asm("mma.sync.aligned.m16n8k16.row.col.f32.bf16.bf16.f32 "
        "{%0,%1,%2,%3}, {%4,%5,%6,%7}, {%8,%9}, {%0,%1,%2,%3};"
        : "+f"(d[0]), "+f"(d[1]), "+f"(d[2]), "+f"(d[3])
        : "r"(a[0]), "r"(a[1]), "r"(a[2]), "r"(a[3]), "r"(b0), "r"(b1));
}
__device__ __forceinline__ void ldsm4(unsigned (&r)[4], unsigned addr) {
    asm volatile("ldmatrix.sync.aligned.m8n8.x4.shared.b16 {%0,%1,%2,%3}, [%4];"
        : "=r"(r[0]), "=r"(r[1]), "=r"(r[2]), "=r"(r[3]) : "r"(addr));
}

// ---------------------------------------------------------------------------
// Kernel 1: mask compaction (unchanged — proven)
// ---------------------------------------------------------------------------
__global__ void compact_kernel(const unsigned char* __restrict__ mask8) {
    __shared__ int warpSum[8];
    int tid  = threadIdx.x;
    int lane = tid & 31, wid = tid >> 5;
    int base = tid * 8;
    int probe = 0;
#pragma unroll
    for (int i = 0; i < 8; i++) {
        int p = base + i;
        if ((p & 3) != 0 && mask8[p] != 0) probe = 1;
    }
    int isU8 = __syncthreads_or(probe);
    const int* mask32 = (const int*)mask8;
    int v[8], c = 0;
#pragma unroll
    for (int i = 0; i < 8; i++) {
        int e = base + i;
        int val = isU8 ? (int)(mask8[e] != 0) : (int)(mask32[e] != 0);
        v[i] = val; c += val;
    }
    int incl = c;
#pragma unroll
    for (int off = 1; off < 32; off <<= 1) {
        int t = __shfl_up_sync(0xffffffffu, incl, off);
        if (lane >= off) incl += t;
    }
    if (lane == 31) warpSum[wid] = incl;
    __syncthreads();
    if (wid == 0) {
        int ws = (lane < 8) ? warpSum[lane] : 0;
#pragma unroll
        for (int off = 1; off < 8; off <<= 1) {
            int t = __shfl_up_sync(0xffffffffu, ws, off);
            if (lane >= off) ws += t;
        }
        if (lane < 8) warpSum[lane] = ws;
    }
    __syncthreads();
    int wbase = (wid > 0) ? warpSum[wid - 1] : 0;
    int idx = wbase + incl - c;
#pragma unroll
    for (int i = 0; i < 8; i++) {
        if (v[i]) {
            g_pos [idx] = base + i;
            g_posf[idx] = (float)(base + i - (SLEN - 1));
            idx++;
        }
    }
    int n = warpSum[7];
    for (int j = n + tid; j < SLEN; j += 256) g_posf[j] = -1.0e30f;
    if (tid == 0) g_nvalid = n;
}

// ---------------------------------------------------------------------------
// Kernel 2: gather + hi/lo split (unchanged — proven)
// ---------------------------------------------------------------------------
__global__ void scatter_kernel(const float* __restrict__ K, const float* __restrict__ V) {
    int h   = blockIdx.y;
    int jin = threadIdx.x & 15;
    int d4  = threadIdx.x >> 4;
    int j   = blockIdx.x * 16 + jin;
    int n   = g_nvalid;
    float4 kk = make_float4(0.f, 0.f, 0.f, 0.f), vv = kk;
    if (j < n) {
        int src = g_pos[j];
        kk = *(const float4*)(K + ((size_t)h * SLEN + src) * HD + d4 * 4);
        vv = *(const float4*)(V + ((size_t)h * SLEN + src) * HD + d4 * 4);
    }
    float ka[4] = {kk.x, kk.y, kk.z, kk.w};
    float va[4] = {vv.x, vv.y, vv.z, vv.w};
    size_t kbase = ((size_t)h * SLEN + j) * HD + 4 * d4;
#pragma unroll
    for (int e = 0; e < 4; e++) {
        __nv_bfloat16 hh = __float2bfloat16(ka[e]);
        __nv_bfloat16 ll = __float2bfloat16(ka[e] - __bfloat162float(hh));
        g_Kh[kbase + e] = hh;
        g_Kl[kbase + e] = ll;
        __nv_bfloat16 vh = __float2bfloat16(va[e]);
        __nv_bfloat16 vl = __float2bfloat16(va[e] - __bfloat162float(vh));
        size_t vt = ((size_t)h * HD + 4 * d4 + e) * SLEN + j;
        g_VtH[vt] = vh;
        g_VtL[vt] = vl;
    }
}

// ---------------------------------------------------------------------------
// prefetch one KT=32 K/V tile (+djs) into a stage via cp.async (256 threads)
// K tile: 256 chunks (8 per 128B row); V tile: 256 chunks (4 per 64B row)
// ---------------------------------------------------------------------------
__device__ __forceinline__ void prefetch_tile(char* smem, int stage, int h, int k0, int tid) {
    unsigned st = smem_u32(smem + stage * STAGE);
    {
        const char* bKh = (const char*)(g_Kh + ((size_t)h * SLEN + k0) * HD);
        const char* bKl = (const char*)(g_Kl + ((size_t)h * SLEN + k0) * HD);
        int row = tid >> 3, c = tid & 7;
        unsigned off = row * (STRK * 2) + c * 16;
        cp16(st + OFF_KH + off, bKh + tid * 16);
        cp16(st + OFF_KL + off, bKl + tid * 16);
    }
    {
        int row = tid >> 2, c = tid & 3;
        unsigned off = row * (STRV * 2) + c * 16;
        cp16(st + OFF_VH + off, (const char*)(g_VtH + ((size_t)h * HD + row) * SLEN + k0) + c * 16);
        cp16(st + OFF_VL + off, (const char*)(g_VtL + ((size_t)h * HD + row) * SLEN + k0) + c * 16);
    }
    if (tid < 8) cp16(st + OFF_DJ + tid * 16, (const char*)(g_posf + k0) + tid * 16);
}

// ---------------------------------------------------------------------------
// Kernel 3: flash attention, mma.sync, 256 threads (8 warps x 16 q-rows),
// QT=128, KT=32, 2 CTAs/SM -> 4 warps/SMSP, single wave.
// ---------------------------------------------------------------------------
__global__ __launch_bounds__(NT, 2) void attn_kernel(const float* __restrict__ Q,
                                                     float* __restrict__ Out) {
    extern __shared__ char smem[];
    int tid = threadIdx.x, w = tid >> 5, lane = tid & 31;
    int t4 = lane & 3, g = lane >> 2;
    int h = blockIdx.y, q0 = blockIdx.x * QT;
    const float scaleL = 0.125f * LOG2E;
    const float slopeL = exp2f(-0.5f * (float)(h + 1)) * LOG2E;
    int n = g_nvalid, ntiles = (n + KT - 1) >> 5;

    prefetch_tile(smem, 0, h, 0, tid);
    cp_commit();

    // ---- Q prologue: two 64-row halves staged through stage-1 region.
    // Warps 0-3 take fragments from half 0 (rows 0..63), warps 4-7 from half 1.
    __nv_bfloat16* Qh = (__nv_bfloat16*)(smem + STAGE);
    __nv_bfloat16* Ql = Qh + 64 * STRK;
    unsigned qbH = smem_u32(Qh), qbL = smem_u32(Ql);
    unsigned qoff = ((16 * (w & 3) + (lane & 15)) * STRK + 8 * (lane >> 4)) * 2;
    unsigned qfh[4][4], qfl[4][4];
#pragma unroll
    for (int gi = 0; gi < 2; gi++) {
        const float* Qg = Q + ((size_t)h * SLEN + q0 + gi * 64) * HD;
        for (int idx = tid; idx < 64 * 16; idx += NT) {
            int row = idx >> 4, c4 = idx & 15;
            float4 v = *(const float4*)(Qg + row * HD + c4 * 4);
            unsigned hp0, lp0, hp1, lp1;
            splitpack(v.x * scaleL, v.y * scaleL, hp0, lp0);
            splitpack(v.z * scaleL, v.w * scaleL, hp1, lp1);
            unsigned off = row * STRK + 4 * c4;
            *(unsigned*)&Qh[off]     = hp0;
            *(unsigned*)&Qh[off + 2] = hp1;
            *(unsigned*)&Ql[off]     = lp0;
            *(unsigned*)&Ql[off + 2] = lp1;
        }
        __syncthreads();
        if ((w >> 2) == gi) {
#pragma unroll
            for (int c = 0; c < 4; c++) {
                ldsm4(qfh[c], qbH + qoff + 32 * c);
                ldsm4(qfl[c], qbL + qoff + 32 * c);
            }
        }
        __syncthreads();   // staging free for next half / stage-1 prefetch
    }

    if (ntiles > 1) prefetch_tile(smem, 1, h, KT, tid);
    cp_commit();

    unsigned koff4 = (((lane & 7) + 8 * (lane >> 4)) * STRK + 8 * ((lane >> 3) & 1)) * 2;
    unsigned voff4 = (((lane & 7) + 8 * (lane >> 4)) * STRV + 8 * ((lane >> 3) & 1)) * 2;

    float oacc[8][4] = {};
    float lS0 = 0.f, lS1 = 0.f;

    for (int tt = 0; tt < ntiles; ++tt) {
        char* st = smem + (tt & 1) * STAGE;
        unsigned kbH = smem_u32(st) + OFF_KH, kbL = smem_u32(st) + OFF_KL;
        unsigned vbH = smem_u32(st) + OFF_VH, vbL = smem_u32(st) + OFF_VL;
        const float* djs = (const float*)(st + OFF_DJ);

        cp_wait<1>();
        __syncthreads();

        // ---- S = Q.K^T (log2 domain), 3-term bf16; 32 j rows per tile ----
        float sacc[4][4];
#pragma unroll
        for (int j = 0; j < 4; j++)
#pragma unroll
            for (int e = 0; e < 4; e++) sacc[j][e] = 0.f;

#pragma unroll
        for (int c = 0; c < 4; c++) {
            unsigned kh[4][2], kl[4][2];
#pragma unroll
            for (int jp = 0; jp < 2; jp++) {
                unsigned r[4];
                unsigned a = koff4 + (jp * 16 * STRK + 16 * c) * 2;
                ldsm4(r, kbH + a);
                kh[2 * jp][0] = r[0]; kh[2 * jp][1] = r[1];
                kh[2 * jp + 1][0] = r[2]; kh[2 * jp + 1][1] = r[3];
                ldsm4(r, kbL + a);
                kl[2 * jp][0] = r[0]; kl[2 * jp][1] = r[1];
                kl[2 * jp + 1][0] = r[2]; kl[2 * jp + 1][1] = r[3];
            }
#pragma unroll
            for (int j = 0; j < 4; j++) mma_bf16(sacc[j], qfh[c], kh[j][0], kh[j][1]);
#pragma unroll
            for (int j = 0; j < 4; j++) mma_bf16(sacc[j], qfh[c], kl[j][0], kl[j][1]);
#pragma unroll
            for (int j = 0; j < 4; j++) mma_bf16(sacc[j], qfl[c], kh[j][0], kh[j][1]);
        }

        // ---- fixed-shift softmax + P splitpack ----
        unsigned ph[2][4], pl[2][4];
#pragma unroll
        for (int j = 0; j < 4; j++) {
            float2 b = *(const float2*)&djs[8 * j + 2 * t4];
            float b0 = fmaf(slopeL, b.x, -FIXM);
            float b1 = fmaf(slopeL, b.y, -FIXM);
            float p0 = ex2(sacc[j][0] + b0);
            float p1 = ex2(sacc[j][1] + b1);
            float p2 = ex2(sacc[j][2] + b0);
            float p3 = ex2(sacc[j][3] + b1);
            lS0 += p0 + p1;
            lS1 += p2 + p3;
            int c = j >> 1, f = (j & 1) * 2;
            splitpack(p0, p1, ph[c][f],     pl[c][f]);
            splitpack(p2, p3, ph[c][f + 1], pl[c][f + 1]);
        }

        // ---- O += P.V (C->A identity, 3-term bf16) ----
#pragma unroll
        for (int c = 0; c < 2; c++) {
            unsigned vh[8][2], vl[8][2];
#pragma unroll
            for (int jp = 0; jp < 4; jp++) {
                unsigned r[4];
                unsigned a = voff4 + (jp * 16 * STRV + 16 * c) * 2;
                ldsm4(r, vbH + a);
                vh[2 * jp][0] = r[0]; vh[2 * jp][1] = r[1];
                vh[2 * jp + 1][0] = r[2]; vh[2 * jp + 1][1] = r[3];
                ldsm4(r, vbL + a);
                vl[2 * jp][0] = r[0]; vl[2 * jp][1] = r[1];
                vl[2 * jp + 1][0] = r[2]; vl[2 * jp + 1][1] = r[3];
            }
#pragma unroll
            for (int dj = 0; dj < 8; dj++) mma_bf16(oacc[dj], ph[c], vh[dj][0], vh[dj][1]);
#pragma unroll
            for (int dj = 0; dj < 8; dj++) mma_bf16(oacc[dj], ph[c], vl[dj][0], vl[dj][1]);
#pragma unroll
            for (int dj = 0; dj < 8; dj++) mma_bf16(oacc[dj], pl[c], vh[dj][0], vh[dj][1]);
        }

        __syncthreads();   // stage fully consumed
        if (tt + 2 < ntiles) prefetch_tile(smem, tt & 1, h, (tt + 2) * KT, tid);
        cp_commit();
    }

    // ---- epilogue: row-sum reduction + store (warp w owns rows 16w..16w+15) ----
    lS0 += __shfl_xor_sync(0xffffffffu, lS0, 1);
    lS0 += __shfl_xor_sync(0xffffffffu, lS0, 2);
    lS1 += __shfl_xor_sync(0xffffffffu, lS1, 1);
    lS1 += __shfl_xor_sync(0xffffffffu, lS1, 2);
    float inv0 = 1.0f / lS0, inv1 = 1.0f / lS1;
    int r0 = q0 + 16 * w + g, r1 = r0 + 8;
    float* O0 = Out + ((size_t)h * SLEN + r0) * HD;
    float* O1 = Out + ((size_t)h * SLEN + r1) * HD;
#pragma unroll
    for (int dj = 0; dj < 8; dj++) {
        int col = 8 * dj + 2 * t4;
        *(float2*)&O0[col] = make_float2(oacc[dj][0] * inv0, oacc[dj][1] * inv0);
        *(float2*)&O1[col] = make_float2(oacc[dj][2] * inv1, oacc[dj][3] * inv1);
    }
}

// ---------------------------------------------------------------------------
extern "C" void kernel_launch(void* const* d_in, const int* in_sizes, int n_in,
                              void* d_out, int out_size) {
    const float*         Q    = (const float*)d_in[0];
    const float*         K    = (const float*)d_in[1];
    const float*         V    = (const float*)d_in[2];
    const unsigned char* mask = (const unsigned char*)d_in[3];
    float*               out  = (float*)d_out;

    cudaFuncSetAttribute(attn_kernel, cudaFuncAttributeMaxDynamicSharedMemorySize, SMEM_BYTES);

    compact_kernel<<<1, 256>>>(mask);
    dim3 gs(SLEN / 16, NH);
    scatter_kernel<<<gs, 256>>>(K, V);
    dim3 ga(SLEN / QT, NH);
    attn_kernel<<<ga, NT, SMEM_BYTES>>>(Q, out);
}

// round 15
// speedup vs baseline: 1.0185x; 1.0185x over previous
#include <cuda_runtime.h>
#include <cuda_bf16.h>

#define SLEN 2048
#define NH   16
#define HD   64
#define QT   128
#define KT   32
#define LOG2E 1.4426950408889634f
#define FIXM 12.0f

// smem stage layout (KT=32): K tiles 32x72 bf16, V^T tiles 64x40 bf16
#define STRK 72
#define STRV 40
#define OFF_KH 0
#define OFF_KL 4608
#define OFF_VH 9216
#define OFF_VL 14336
#define OFF_DJ 19456
#define STAGE  19584
#define SMEM_BYTES (2 * STAGE)   // 39168

// Scratch (allocation-free rule) — layouts identical to R7/R12
__device__ __nv_bfloat16 g_Kh [NH * SLEN * HD];   // K rows [h][j][d], hi
__device__ __nv_bfloat16 g_Kl [NH * SLEN * HD];
__device__ __nv_bfloat16 g_VtH[NH * HD * SLEN];   // V transposed [h][d][j]
__device__ __nv_bfloat16 g_VtL[NH * HD * SLEN];
__device__ float g_posf[SLEN];
__device__ int   g_pos [SLEN];
__device__ int   g_nvalid;

// ---- helpers ----------------------------------------------------------------
__device__ __forceinline__ unsigned smem_u32(const void* p) {
    return (unsigned)__cvta_generic_to_shared(p);
}
__device__ __forceinline__ float ex2(float x) {
    float r; asm("ex2.approx.f32 %0, %1;" : "=f"(r) : "f"(x)); return r;
}
__device__ __forceinline__ void splitpack(float x0, float x1, unsigned& hp, unsigned& lp) {
    __nv_bfloat16 h0 = __float2bfloat16(x0), h1 = __float2bfloat16(x1);
    float r0 = x0 - __bfloat162float(h0), r1 = x1 - __bfloat162float(h1);
    __nv_bfloat16 l0 = __float2bfloat16(r0), l1 = __float2bfloat16(r1);
    hp = ((unsigned)__bfloat16_as_ushort(h1) << 16) | (unsigned)__bfloat16_as_ushort(h0);
    lp = ((unsigned)__bfloat16_as_ushort(l1) << 16) | (unsigned)__bfloat16_as_ushort(l0);
}
__device__ __forceinline__ void cp16(unsigned dst, const void* src) {
    asm volatile("cp.async.cg.shared.global [%0], [%1], 16;" :: "r"(dst), "l"(src));
}
__device__ __forceinline__ void cp_commit() { asm volatile("cp.async.commit_group;"); }
template<int N> __device__ __forceinline__ void cp_wait() {
    asm volatile("cp.async.wait_group %0;" :: "n"(N));
}
__device__ __forceinline__ void mma_bf16(float (&d)[4], const unsigned (&a)[4],
                                         unsigned b0, unsigned b1) {
    asm("mma.sync.aligned.m16n8k16.row.col.f32.bf16.bf16.f32 "
        "{%0,%1,%2,%3}, {%4,%5,%6,%7}, {%8,%9}, {%0,%1,%2,%3};"
        : "+f"(d[0]), "+f"(d[1]), "+f"(d[2]), "+f"(d[3])
        : "r"(a[0]), "r"(a[1]), "r"(a[2]), "r"(a[3]), "r"(b0), "r"(b1));
}
__device__ __forceinline__ void ldsm4(unsigned (&r)[4], unsigned addr) {
    asm volatile("ldmatrix.sync.aligned.m8n8.x4.shared.b16 {%0,%1,%2,%3}, [%4];"
        : "=r"(r[0]), "=r"(r[1]), "=r"(r[2]), "=r"(r[3]) : "r"(addr));
}

// ---------------------------------------------------------------------------
// Kernel 1: mask compaction (unchanged — proven)
// ---------------------------------------------------------------------------
__global__ void compact_kernel(const unsigned char* __restrict__ mask8) {
    __shared__ int warpSum[8];
    int tid  = threadIdx.x;
    int lane = tid & 31, wid = tid >> 5;
    int base = tid * 8;
    int probe = 0;
#pragma unroll
    for (int i = 0; i < 8; i++) {
        int p = base + i;
        if ((p & 3) != 0 && mask8[p] != 0) probe = 1;
    }
    int isU8 = __syncthreads_or(probe);
    const int* mask32 = (const int*)mask8;
    int v[8], c = 0;
#pragma unroll
    for (int i = 0; i < 8; i++) {
        int e = base + i;
        int val = isU8 ? (int)(mask8[e] != 0) : (int)(mask32[e] != 0);
        v[i] = val; c += val;
    }
    int incl = c;
#pragma unroll
    for (int off = 1; off < 32; off <<= 1) {
        int t = __shfl_up_sync(0xffffffffu, incl, off);
        if (lane >= off) incl += t;
    }
    if (lane == 31) warpSum[wid] = incl;
    __syncthreads();
    if (wid == 0) {
        int ws = (lane < 8) ? warpSum[lane] : 0;
#pragma unroll
        for (int off = 1; off < 8; off <<= 1) {
            int t = __shfl_up_sync(0xffffffffu, ws, off);
            if (lane >= off) ws += t;
        }
        if (lane < 8) warpSum[lane] = ws;
    }
    __syncthreads();
    int wbase = (wid > 0) ? warpSum[wid - 1] : 0;
    int idx = wbase + incl - c;
#pragma unroll
    for (int i = 0; i < 8; i++) {
        if (v[i]) {
            g_pos [idx] = base + i;
            g_posf[idx] = (float)(base + i - (SLEN - 1));
            idx++;
        }
    }
    int n = warpSum[7];
    for (int j = n + tid; j < SLEN; j += 256) g_posf[j] = -1.0e30f;
    if (tid == 0) g_nvalid = n;
}

// ---------------------------------------------------------------------------
// Kernel 2: gather + hi/lo split (unchanged — proven)
// ---------------------------------------------------------------------------
__global__ void scatter_kernel(const float* __restrict__ K, const float* __restrict__ V) {
    int h   = blockIdx.y;
    int jin = threadIdx.x & 15;
    int d4  = threadIdx.x >> 4;
    int j   = blockIdx.x * 16 + jin;
    int n   = g_nvalid;
    float4 kk = make_float4(0.f, 0.f, 0.f, 0.f), vv = kk;
    if (j < n) {
        int src = g_pos[j];
        kk = *(const float4*)(K + ((size_t)h * SLEN + src) * HD + d4 * 4);
        vv = *(const float4*)(V + ((size_t)h * SLEN + src) * HD + d4 * 4);
    }
    float ka[4] = {kk.x, kk.y, kk.z, kk.w};
    float va[4] = {vv.x, vv.y, vv.z, vv.w};
    size_t kbase = ((size_t)h * SLEN + j) * HD + 4 * d4;
#pragma unroll
    for (int e = 0; e < 4; e++) {
        __nv_bfloat16 hh = __float2bfloat16(ka[e]);
        __nv_bfloat16 ll = __float2bfloat16(ka[e] - __bfloat162float(hh));
        g_Kh[kbase + e] = hh;
        g_Kl[kbase + e] = ll;
        __nv_bfloat16 vh = __float2bfloat16(va[e]);
        __nv_bfloat16 vl = __float2bfloat16(va[e] - __bfloat162float(vh));
        size_t vt = ((size_t)h * HD + 4 * d4 + e) * SLEN + j;
        g_VtH[vt] = vh;
        g_VtL[vt] = vl;
    }
}

// ---------------------------------------------------------------------------
// prefetch one KT=32 K/V tile (+djs) into a stage via cp.async (R12, proven)
// ---------------------------------------------------------------------------
__device__ __forceinline__ void prefetch_tile(char* smem, int stage, int h, int k0, int tid) {
    unsigned st = smem_u32(smem + stage * STAGE);
    const char* bKh = (const char*)(g_Kh + ((size_t)h * SLEN + k0) * HD);
    const char* bKl = (const char*)(g_Kl + ((size_t)h * SLEN + k0) * HD);
#pragma unroll
    for (int i = 0; i < 2; i++) {   // K hi/lo: 256 chunks each (8 per 128B row)
        int idx = tid + 128 * i;
        int row = idx >> 3, c = idx & 7;
        unsigned off = row * (STRK * 2) + c * 16;
        cp16(st + OFF_KH + off, bKh + idx * 16);
        cp16(st + OFF_KL + off, bKl + idx * 16);
    }
#pragma unroll
    for (int i = 0; i < 2; i++) {   // V hi/lo: 256 chunks each (4 per 64B row)
        int idx = tid + 128 * i;
        int row = idx >> 2, c = idx & 3;
        unsigned off = row * (STRV * 2) + c * 16;
        cp16(st + OFF_VH + off, (const char*)(g_VtH + ((size_t)h * HD + row) * SLEN + k0) + c * 16);
        cp16(st + OFF_VL + off, (const char*)(g_VtL + ((size_t)h * HD + row) * SLEN + k0) + c * 16);
    }
    if (tid < 8) cp16(st + OFF_DJ + tid * 16, (const char*)(g_posf + k0) + tid * 16);
}

// ---------------------------------------------------------------------------
// Kernel 3: flash attention, mma.sync, QT=128 (2 q-groups/warp), software-
// pipelined: PV(t) interleaved with S(t+1) in one merged mma region.
// ---------------------------------------------------------------------------
__global__ __launch_bounds__(128, 2) void attn_kernel(const float* __restrict__ Q,
                                                      float* __restrict__ Out) {
    extern __shared__ char smem[];
    int tid = threadIdx.x, w = tid >> 5, lane = tid & 31;
    int t4 = lane & 3, g = lane >> 2;
    int h = blockIdx.y, q0 = blockIdx.x * QT;
    const float scaleL = 0.125f * LOG2E;
    const float slopeL = exp2f(-0.5f * (float)(h + 1)) * LOG2E;
    int n = g_nvalid, ntiles = (n + KT - 1) >> 5;

    prefetch_tile(smem, 0, h, 0, tid);
    cp_commit();

    // ---- Q prologue: two 64-row halves staged through stage-1 region ----
    __nv_bfloat16* Qh = (__nv_bfloat16*)(smem + STAGE);
    __nv_bfloat16* Ql = Qh + 64 * STRK;
    unsigned qbH = smem_u32(Qh), qbL = smem_u32(Ql);
    unsigned qoff = ((16 * w + (lane & 15)) * STRK + 8 * (lane >> 4)) * 2;
    unsigned qfh[2][4][4], qfl[2][4][4];
#pragma unroll
    for (int gi = 0; gi < 2; gi++) {
        const float* Qg = Q + ((size_t)h * SLEN + q0 + gi * 64) * HD;
        for (int idx = tid; idx < 64 * 16; idx += 128) {
            int row = idx >> 4, c4 = idx & 15;
            float4 v = *(const float4*)(Qg + row * HD + c4 * 4);
            unsigned hp0, lp0, hp1, lp1;
            splitpack(v.x * scaleL, v.y * scaleL, hp0, lp0);
            splitpack(v.z * scaleL, v.w * scaleL, hp1, lp1);
            unsigned off = row * STRK + 4 * c4;
            *(unsigned*)&Qh[off]     = hp0;
            *(unsigned*)&Qh[off + 2] = hp1;
            *(unsigned*)&Ql[off]     = lp0;
            *(unsigned*)&Ql[off + 2] = lp1;
        }
        __syncthreads();
#pragma unroll
        for (int c = 0; c < 4; c++) {
            ldsm4(qfh[gi][c], qbH + qoff + 32 * c);
            ldsm4(qfl[gi][c], qbL + qoff + 32 * c);
        }
        __syncthreads();   // staging free for next half / stage-1 prefetch
    }

    if (ntiles > 1) prefetch_tile(smem, 1, h, KT, tid);
    cp_commit();   // unconditional: keeps group count = 2

    unsigned koff4 = (((lane & 7) + 8 * (lane >> 4)) * STRK + 8 * ((lane >> 3) & 1)) * 2;
    unsigned voff4 = (((lane & 7) + 8 * (lane >> 4)) * STRV + 8 * ((lane >> 3) & 1)) * 2;

    float oacc[2][8][4] = {};
    float lS[2][2] = {};
    float sacc[2][4][4];

    // ---- S(0) prologue ----
    cp_wait<1>();      // stage 0 complete (prefetch(1) may still be in flight)
    __syncthreads();
#pragma unroll
    for (int gi = 0; gi < 2; gi++)
#pragma unroll
        for (int j = 0; j < 4; j++)
#pragma unroll
            for (int e = 0; e < 4; e++) sacc[gi][j][e] = 0.f;
    {
        unsigned kbH = smem_u32(smem) + OFF_KH, kbL = smem_u32(smem) + OFF_KL;
#pragma unroll
        for (int c = 0; c < 4; c++) {
#pragma unroll
            for (int jp = 0; jp < 2; jp++) {
                unsigned rh[4], rl[4];
                unsigned a = koff4 + (jp * 16 * STRK + 16 * c) * 2;
                ldsm4(rh, kbH + a);
                ldsm4(rl, kbL + a);
#pragma unroll
                for (int gi = 0; gi < 2; gi++) {
                    mma_bf16(sacc[gi][2 * jp],     qfh[gi][c], rh[0], rh[1]);
                    mma_bf16(sacc[gi][2 * jp + 1], qfh[gi][c], rh[2], rh[3]);
                    mma_bf16(sacc[gi][2 * jp],     qfh[gi][c], rl[0], rl[1]);
                    mma_bf16(sacc[gi][2 * jp + 1], qfh[gi][c], rl[2], rl[3]);
                    mma_bf16(sacc[gi][2 * jp],     qfl[gi][c], rh[0], rh[1]);
                    mma_bf16(sacc[gi][2 * jp + 1], qfl[gi][c], rh[2], rh[3]);
                }
            }
        }
    }

    // ---- main loop: softmax(t) -> [PV(t) || S(t+1)] merged ----
    for (int tt = 0; tt < ntiles; ++tt) {
        int cur = tt & 1, nxt = cur ^ 1;
        char* stc = smem + cur * STAGE;
        const float* djs = (const float*)(stc + OFF_DJ);
        bool has_next = (tt + 1 < ntiles);

        // softmax(t): sacc -> ph/pl + lS  (sacc dead after)
        unsigned ph[2][2][4], pl[2][2][4];
#pragma unroll
        for (int gi = 0; gi < 2; gi++) {
#pragma unroll
            for (int j = 0; j < 4; j++) {
                float2 b = *(const float2*)&djs[8 * j + 2 * t4];
                float b0 = fmaf(slopeL, b.x, -FIXM);
                float b1 = fmaf(slopeL, b.y, -FIXM);
                float p0 = ex2(sacc[gi][j][0] + b0);
                float p1 = ex2(sacc[gi][j][1] + b1);
                float p2 = ex2(sacc[gi][j][2] + b0);
                float p3 = ex2(sacc[gi][j][3] + b1);
                lS[gi][0] += p0 + p1;
                lS[gi][1] += p2 + p3;
                int c = j >> 1, f = (j & 1) * 2;
                splitpack(p0, p1, ph[gi][c][f],     pl[gi][c][f]);
                splitpack(p2, p3, ph[gi][c][f + 1], pl[gi][c][f + 1]);
            }
        }

        // stage t+1 visible to all warps before K(t+1) ldsm
        if (has_next) cp_wait<0>();
        __syncthreads();

        // zero next-S accumulators
#pragma unroll
        for (int gi = 0; gi < 2; gi++)
#pragma unroll
            for (int j = 0; j < 4; j++)
#pragma unroll
                for (int e = 0; e < 4; e++) sacc[gi][j][e] = 0.f;

        unsigned knH = smem_u32(smem + nxt * STAGE) + OFF_KH;
        unsigned knL = smem_u32(smem + nxt * STAGE) + OFF_KL;
        unsigned vbH = smem_u32(stc) + OFF_VH, vbL = smem_u32(stc) + OFF_VL;

        // merged region: S(t+1) and PV(t) are independent mma streams
#pragma unroll
        for (int c = 0; c < 4; c++) {
            if (has_next) {
#pragma unroll
                for (int jp = 0; jp < 2; jp++) {
                    unsigned rh[4], rl[4];
                    unsigned a = koff4 + (jp * 16 * STRK + 16 * c) * 2;
                    ldsm4(rh, knH + a);
                    ldsm4(rl, knL + a);
#pragma unroll
                    for (int gi = 0; gi < 2; gi++) {
                        mma_bf16(sacc[gi][2 * jp],     qfh[gi][c], rh[0], rh[1]);
                        mma_bf16(sacc[gi][2 * jp + 1], qfh[gi][c], rh[2], rh[3]);
                        mma_bf16(sacc[gi][2 * jp],     qfh[gi][c], rl[0], rl[1]);
                        mma_bf16(sacc[gi][2 * jp + 1], qfh[gi][c], rl[2], rl[3]);
                        mma_bf16(sacc[gi][2 * jp],     qfl[gi][c], rh[0], rh[1]);
                        mma_bf16(sacc[gi][2 * jp + 1], qfl[gi][c], rh[2], rh[3]);
                    }
                }
            }
            if (c < 2) {
#pragma unroll
                for (int jp = 0; jp < 4; jp++) {
                    unsigned rh[4], rl[4];
                    unsigned a = voff4 + (jp * 16 * STRV + 16 * c) * 2;
                    ldsm4(rh, vbH + a);
                    ldsm4(rl, vbL + a);
#pragma unroll
                    for (int gi = 0; gi < 2; gi++) {
                        mma_bf16(oacc[gi][2 * jp],     ph[gi][c], rh[0], rh[1]);
                        mma_bf16(oacc[gi][2 * jp + 1], ph[gi][c], rh[2], rh[3]);
                        mma_bf16(oacc[gi][2 * jp],     ph[gi][c], rl[0], rl[1]);
                        mma_bf16(oacc[gi][2 * jp + 1], ph[gi][c], rl[2], rl[3]);
                        mma_bf16(oacc[gi][2 * jp],     pl[gi][c], rh[0], rh[1]);
                        mma_bf16(oacc[gi][2 * jp + 1], pl[gi][c], rh[2], rh[3]);
                    }
                }
            }
        }

        __syncthreads();   // stage `cur` fully consumed by all warps
        if (tt + 2 < ntiles) prefetch_tile(smem, cur, h, (tt + 2) * KT, tid);
        cp_commit();
    }

    // ---- epilogue: per-group row-sum reduction + store ----
#pragma unroll
    for (int gi = 0; gi < 2; gi++) {
        float l0 = lS[gi][0], l1 = lS[gi][1];
        l0 += __shfl_xor_sync(0xffffffffu, l0, 1);
        l0 += __shfl_xor_sync(0xffffffffu, l0, 2);
        l1 += __shfl_xor_sync(0xffffffffu, l1, 1);
        l1 += __shfl_xor_sync(0xffffffffu, l1, 2);
        float inv0 = 1.0f / l0, inv1 = 1.0f / l1;
        int r0 = q0 + gi * 64 + 16 * w + g, r1 = r0 + 8;
        float* O0 = Out + ((size_t)h * SLEN + r0) * HD;
        float* O1 = Out + ((size_t)h * SLEN + r1) * HD;
#pragma unroll
        for (int dj = 0; dj < 8; dj++) {
            int col = 8 * dj + 2 * t4;
            *(float2*)&O0[col] = make_float2(oacc[gi][dj][0] * inv0, oacc[gi][dj][1] * inv0);
            *(float2*)&O1[col] = make_float2(oacc[gi][dj][2] * inv1, oacc[gi][dj][3] * inv1);
        }
    }
}

// ---------------------------------------------------------------------------
extern "C" void kernel_launch(void* const* d_in, const int* in_sizes, int n_in,
                              void* d_out, int out_size) {
    const float*         Q    = (const float*)d_in[0];
    const float*         K    = (const float*)d_in[1];
    const float*         V    = (const float*)d_in[2];
    const unsigned char* mask = (const unsigned char*)d_in[3];
    float*               out  = (float*)d_out;

    cudaFuncSetAttribute(attn_kernel, cudaFuncAttributeMaxDynamicSharedMemorySize, SMEM_BYTES);

    compact_kernel<<<1, 256>>>(mask);
    dim3 gs(SLEN / 16, NH);
    scatter_kernel<<<gs, 256>>>(K, V);
    dim3 ga(SLEN / QT, NH);
    attn_kernel<<<ga, 128, SMEM_BYTES>>>(Q, out);
}

// round 16
// speedup vs baseline: 2.4612x; 2.4165x over previous
#include <cuda_runtime.h>
#include <cuda_bf16.h>
#include <cuda_fp16.h>

#define SLEN 2048
#define NH   16
#define HD   64
#define QT   128
#define KT   64
#define LOG2E 1.4426950408889634f
#define FIXM 12.0f

// smem stage: K tile 64(j)x64(d) fp16 rows padded to 72, V^T tile 64(d)x64(j)
#define STRK 72
#define STRV 72
#define OFF_K  0
#define OFF_V  9216
#define OFF_DJ 18432
#define STAGE  18688
#define SMEM_BYTES (2 * STAGE)   // 37376

// Scratch (allocation-free rule): single-fp16 planes
__device__ __half g_K16 [NH * SLEN * HD];   // K rows [h][j][d]
__device__ __half g_Vt16[NH * HD * SLEN];   // V transposed [h][d][j]
__device__ float g_posf[SLEN];
__device__ int   g_pos [SLEN];
__device__ int   g_nvalid;

// ---- helpers ----------------------------------------------------------------
__device__ __forceinline__ unsigned smem_u32(const void* p) {
    return (unsigned)__cvta_generic_to_shared(p);
}
__device__ __forceinline__ float ex2(float x) {
    float r; asm("ex2.approx.f32 %0, %1;" : "=f"(r) : "f"(x)); return r;
}
__device__ __forceinline__ unsigned packh2(float x, float y) {
    __half2 t = __float22half2_rn(make_float2(x, y));
    return *(unsigned*)&t;
}
__device__ __forceinline__ void cp16(unsigned dst, const void* src) {
    asm volatile("cp.async.cg.shared.global [%0], [%1], 16;" :: "r"(dst), "l"(src));
}
__device__ __forceinline__ void cp_commit() { asm volatile("cp.async.commit_group;"); }
template<int N> __device__ __forceinline__ void cp_wait() {
    asm volatile("cp.async.wait_group %0;" :: "n"(N));
}
__device__ __forceinline__ void mma_f16(float (&d)[4], const unsigned (&a)[4],
                                        unsigned b0, unsigned b1) {
    asm("mma.sync.aligned.m16n8k16.row.col.f32.f16.f16.f32 "
        "{%0,%1,%2,%3}, {%4,%5,%6,%7}, {%8,%9}, {%0,%1,%2,%3};"
        : "+f"(d[0]), "+f"(d[1]), "+f"(d[2]), "+f"(d[3])
        : "r"(a[0]), "r"(a[1]), "r"(a[2]), "r"(a[3]), "r"(b0), "r"(b1));
}
__device__ __forceinline__ void ldsm4(unsigned (&r)[4], unsigned addr) {
    asm volatile("ldmatrix.sync.aligned.m8n8.x4.shared.b16 {%0,%1,%2,%3}, [%4];"
        : "=r"(r[0]), "=r"(r[1]), "=r"(r[2]), "=r"(r[3]) : "r"(addr));
}

// ---------------------------------------------------------------------------
// Kernel 1: mask compaction (unchanged — proven)
// ---------------------------------------------------------------------------
__global__ void compact_kernel(const unsigned char* __restrict__ mask8) {
    __shared__ int warpSum[8];
    int tid  = threadIdx.x;
    int lane = tid & 31, wid = tid >> 5;
    int base = tid * 8;
    int probe = 0;
#pragma unroll
    for (int i = 0; i < 8; i++) {
        int p = base + i;
        if ((p & 3) != 0 && mask8[p] != 0) probe = 1;
    }
    int isU8 = __syncthreads_or(probe);
    const int* mask32 = (const int*)mask8;
    int v[8], c = 0;
#pragma unroll
    for (int i = 0; i < 8; i++) {
        int e = base + i;
        int val = isU8 ? (int)(mask8[e] != 0) : (int)(mask32[e] != 0);
        v[i] = val; c += val;
    }
    int incl = c;
#pragma unroll
    for (int off = 1; off < 32; off <<= 1) {
        int t = __shfl_up_sync(0xffffffffu, incl, off);
        if (lane >= off) incl += t;
    }
    if (lane == 31) warpSum[wid] = incl;
    __syncthreads();
    if (wid == 0) {
        int ws = (lane < 8) ? warpSum[lane] : 0;
#pragma unroll
        for (int off = 1; off < 8; off <<= 1) {
            int t = __shfl_up_sync(0xffffffffu, ws, off);
            if (lane >= off) ws += t;
        }
        if (lane < 8) warpSum[lane] = ws;
    }
    __syncthreads();
    int wbase = (wid > 0) ? warpSum[wid - 1] : 0;
    int idx = wbase + incl - c;
#pragma unroll
    for (int i = 0; i < 8; i++) {
        if (v[i]) {
            g_pos [idx] = base + i;
            g_posf[idx] = (float)(base + i - (SLEN - 1));
            idx++;
        }
    }
    int n = warpSum[7];
    for (int j = n + tid; j < SLEN; j += 256) g_posf[j] = -1.0e30f;
    if (tid == 0) g_nvalid = n;
}

// ---------------------------------------------------------------------------
// Kernel 2: gather + fp32->fp16 convert. K rows [h][j][d]; V^T [h][d][j].
// ---------------------------------------------------------------------------
__global__ void scatter_kernel(const float* __restrict__ K, const float* __restrict__ V) {
    int h   = blockIdx.y;
    int jin = threadIdx.x & 15;
    int d4  = threadIdx.x >> 4;
    int j   = blockIdx.x * 16 + jin;
    int n   = g_nvalid;
    float4 kk = make_float4(0.f, 0.f, 0.f, 0.f), vv = kk;
    if (j < n) {
        int src = g_pos[j];
        kk = *(const float4*)(K + ((size_t)h * SLEN + src) * HD + d4 * 4);
        vv = *(const float4*)(V + ((size_t)h * SLEN + src) * HD + d4 * 4);
    }
    // K: pack 4 fp16 = 8 bytes, coalesced
    __half2 k01 = __float22half2_rn(make_float2(kk.x, kk.y));
    __half2 k23 = __float22half2_rn(make_float2(kk.z, kk.w));
    *(__half2*)(g_K16 + ((size_t)h * SLEN + j) * HD + 4 * d4)     = k01;
    *(__half2*)(g_K16 + ((size_t)h * SLEN + j) * HD + 4 * d4 + 2) = k23;
    // V transposed: scalar stores, lanes = consecutive j -> coalesced per row
    float va[4] = {vv.x, vv.y, vv.z, vv.w};
#pragma unroll
    for (int e = 0; e < 4; e++) {
        g_Vt16[((size_t)h * HD + 4 * d4 + e) * SLEN + j] = __float2half_rn(va[e]);
    }
}

// ---------------------------------------------------------------------------
// prefetch one KT=64 K/V tile (+djs) into a stage via cp.async
// K tile: 64 rows x 128B = 512 chunks; V tile: 64 rows x 128B = 512 chunks
// ---------------------------------------------------------------------------
__device__ __forceinline__ void prefetch_tile(char* smem, int stage, int h, int k0, int tid) {
    unsigned st = smem_u32(smem + stage * STAGE);
    const char* bK = (const char*)(g_K16 + ((size_t)h * SLEN + k0) * HD);
#pragma unroll
    for (int i = 0; i < 4; i++) {
        int idx = tid + 128 * i;
        int row = idx >> 3, c = idx & 7;
        unsigned off = row * (STRK * 2) + c * 16;
        cp16(st + OFF_K + off, bK + idx * 16);
        cp16(st + OFF_V + off, (const char*)(g_Vt16 + ((size_t)h * HD + row) * SLEN + k0) + c * 16);
    }
    if (tid < 16) cp16(st + OFF_DJ + tid * 16, (const char*)(g_posf + k0) + tid * 16);
}

// ---------------------------------------------------------------------------
// Kernel 3: flash attention, single-fp16 mma.sync (1 term per GEMM),
// QT=128 (2 q-groups/warp), KT=64, 2-stage cp.async.
// ---------------------------------------------------------------------------
__global__ __launch_bounds__(128, 2) void attn_kernel(const float* __restrict__ Q,
                                                      float* __restrict__ Out) {
    extern __shared__ char smem[];
    int tid = threadIdx.x, w = tid >> 5, lane = tid & 31;
    int t4 = lane & 3, g = lane >> 2;
    int h = blockIdx.y, q0 = blockIdx.x * QT;
    const float scaleL = 0.125f * LOG2E;
    const float slopeL = exp2f(-0.5f * (float)(h + 1)) * LOG2E;
    int n = g_nvalid, ntiles = (n + KT - 1) >> 6;

    prefetch_tile(smem, 0, h, 0, tid);
    cp_commit();

    // ---- Q prologue: two 64-row halves staged through stage-1 region ----
    __half* Qs = (__half*)(smem + STAGE);
    unsigned qb = smem_u32(Qs);
    unsigned qoff = ((16 * w + (lane & 15)) * STRK + 8 * (lane >> 4)) * 2;
    unsigned qf[2][4][4];
#pragma unroll
    for (int gi = 0; gi < 2; gi++) {
        const float* Qg = Q + ((size_t)h * SLEN + q0 + gi * 64) * HD;
        for (int idx = tid; idx < 64 * 16; idx += 128) {
            int row = idx >> 4, c4 = idx & 15;
            float4 v = *(const float4*)(Qg + row * HD + c4 * 4);
            unsigned p01 = packh2(v.x * scaleL, v.y * scaleL);
            unsigned p23 = packh2(v.z * scaleL, v.w * scaleL);
            unsigned off = row * STRK + 4 * c4;
            *(unsigned*)&Qs[off]     = p01;
            *(unsigned*)&Qs[off + 2] = p23;
        }
        __syncthreads();
#pragma unroll
        for (int c = 0; c < 4; c++) ldsm4(qf[gi][c], qb + qoff + 32 * c);
        __syncthreads();   // staging free for next half / stage-1 prefetch
    }

    if (ntiles > 1) prefetch_tile(smem, 1, h, KT, tid);
    cp_commit();

    unsigned koff4 = (((lane & 7) + 8 * (lane >> 4)) * STRK + 8 * ((lane >> 3) & 1)) * 2;
    unsigned voff4 = (((lane & 7) + 8 * (lane >> 4)) * STRV + 8 * ((lane >> 3) & 1)) * 2;

    float oacc[2][8][4] = {};
    float lS[2][2] = {};

    for (int tt = 0; tt < ntiles; ++tt) {
        char* st = smem + (tt & 1) * STAGE;
        unsigned kb = smem_u32(st) + OFF_K;
        unsigned vb = smem_u32(st) + OFF_V;
        const float* djs = (const float*)(st + OFF_DJ);

        cp_wait<1>();
        __syncthreads();

        // ---- S = Q.K^T (log2 domain), single fp16; 64 j rows per tile ----
        float sacc[2][8][4];
#pragma unroll
        for (int gi = 0; gi < 2; gi++)
#pragma unroll
            for (int j = 0; j < 8; j++)
#pragma unroll
                for (int e = 0; e < 4; e++) sacc[gi][j][e] = 0.f;

#pragma unroll
        for (int c = 0; c < 4; c++) {
            unsigned kf[8][2];
#pragma unroll
            for (int jp = 0; jp < 4; jp++) {
                unsigned r[4];
                unsigned a = koff4 + (jp * 16 * STRK + 16 * c) * 2;
                ldsm4(r, kb + a);
                kf[2 * jp][0] = r[0]; kf[2 * jp][1] = r[1];
                kf[2 * jp + 1][0] = r[2]; kf[2 * jp + 1][1] = r[3];
            }
#pragma unroll
            for (int gi = 0; gi < 2; gi++)
#pragma unroll
                for (int j = 0; j < 8; j++)
                    mma_f16(sacc[gi][j], qf[gi][c], kf[j][0], kf[j][1]);
        }

        // ---- fixed-shift softmax; P packed directly to fp16 A-frags ----
        unsigned pA[2][4][4];
#pragma unroll
        for (int gi = 0; gi < 2; gi++) {
#pragma unroll
            for (int j = 0; j < 8; j++) {
                float2 b = *(const float2*)&djs[8 * j + 2 * t4];
                float b0 = fmaf(slopeL, b.x, -FIXM);
                float b1 = fmaf(slopeL, b.y, -FIXM);
                float p0 = ex2(sacc[gi][j][0] + b0);
                float p1 = ex2(sacc[gi][j][1] + b1);
                float p2 = ex2(sacc[gi][j][2] + b0);
                float p3 = ex2(sacc[gi][j][3] + b1);
                lS[gi][0] += p0 + p1;
                lS[gi][1] += p2 + p3;
                int c = j >> 1, f = (j & 1) * 2;
                pA[gi][c][f]     = packh2(p0, p1);
                pA[gi][c][f + 1] = packh2(p2, p3);
            }
        }

        // ---- O += P.V, single fp16 ----
#pragma unroll
        for (int c = 0; c < 4; c++) {
            unsigned vf[8][2];
#pragma unroll
            for (int jp = 0; jp < 4; jp++) {
                unsigned r[4];
                unsigned a = voff4 + (jp * 16 * STRV + 16 * c) * 2;
                ldsm4(r, vb + a);
                vf[2 * jp][0] = r[0]; vf[2 * jp][1] = r[1];
                vf[2 * jp + 1][0] = r[2]; vf[2 * jp + 1][1] = r[3];
            }
#pragma unroll
            for (int gi = 0; gi < 2; gi++)
#pragma unroll
                for (int dj = 0; dj < 8; dj++)
                    mma_f16(oacc[gi][dj], pA[gi][c], vf[dj][0], vf[dj][1]);
        }

        __syncthreads();   // stage fully consumed
        if (tt + 2 < ntiles) prefetch_tile(smem, tt & 1, h, (tt + 2) * KT, tid);
        cp_commit();
    }

    // ---- epilogue: per-group row-sum reduction + store ----
#pragma unroll
    for (int gi = 0; gi < 2; gi++) {
        float l0 = lS[gi][0], l1 = lS[gi][1];
        l0 += __shfl_xor_sync(0xffffffffu, l0, 1);
        l0 += __shfl_xor_sync(0xffffffffu, l0, 2);
        l1 += __shfl_xor_sync(0xffffffffu, l1, 1);
        l1 += __shfl_xor_sync(0xffffffffu, l1, 2);
        float inv0 = 1.0f / l0, inv1 = 1.0f / l1;
        int r0 = q0 + gi * 64 + 16 * w + g, r1 = r0 + 8;
        float* O0 = Out + ((size_t)h * SLEN + r0) * HD;
        float* O1 = Out + ((size_t)h * SLEN + r1) * HD;
#pragma unroll
        for (int dj = 0; dj < 8; dj++) {
            int col = 8 * dj + 2 * t4;
            *(float2*)&O0[col] = make_float2(oacc[gi][dj][0] * inv0, oacc[gi][dj][1] * inv0);
            *(float2*)&O1[col] = make_float2(oacc[gi][dj][2] * inv1, oacc[gi][dj][3] * inv1);
        }
    }
}

// ---------------------------------------------------------------------------
extern "C" void kernel_launch(void* const* d_in, const int* in_sizes, int n_in,
                              void* d_out, int out_size) {
    const float*         Q    = (const float*)d_in[0];
    const float*         K    = (const float*)d_in[1];
    const float*         V    = (const float*)d_in[2];
    const unsigned char* mask = (const unsigned char*)d_in[3];
    float*               out  = (float*)d_out;

    cudaFuncSetAttribute(attn_kernel, cudaFuncAttributeMaxDynamicSharedMemorySize, SMEM_BYTES);

    compact_kernel<<<1, 256>>>(mask);
    dim3 gs(SLEN / 16, NH);
    scatter_kernel<<<gs, 256>>>(K, V);
    dim3 ga(SLEN / QT, NH);
    attn_kernel<<<ga, 128, SMEM_BYTES>>>(Q, out);
}